// round 10
// baseline (speedup 1.0000x reference)
#include <cuda_runtime.h>
#include <math.h>

#define NB 64          // batch
#define SEQ 64         // seq len
#define MD 256         // model dim
#define HF 128         // half
#define WD 300         // word dim
#define MLPD 1024
#define NC 3
#define BKT 8          // K tile
#define NKT (MD / BKT) // 32 k-tiles
#define XP 36          // Xs row stride in floats (pad; 16B-aligned)

// Scratch (device globals — no runtime allocation allowed).
// comp/lgpart ping-pong by layer parity (cw); states ping-pong by sin.
__device__ float g_states[2][NB * SEQ * MD];
__device__ float g_comp[2][NB * (SEQ - 1) * MD];
__device__ float g_lgpart[2][NB * (SEQ - 1) * 2];

__device__ __forceinline__ float sig_f(float x) { return 1.0f / (1.0f + __expf(-x)); }
__device__ __forceinline__ float tanh_f(float x) { return 1.0f - 2.0f / (__expf(2.0f * x) + 1.0f); }

// Packed f32x2 helpers (sm_100a; ptxas never auto-fuses these)
__device__ __forceinline__ unsigned long long pack2(float lo, float hi) {
    unsigned long long p;
    asm("mov.b64 %0, {%1, %2};" : "=l"(p) : "f"(lo), "f"(hi));
    return p;
}
__device__ __forceinline__ void unpack2(unsigned long long p, float& lo, float& hi) {
    asm("mov.b64 {%0, %1}, %2;" : "=f"(lo), "=f"(hi) : "l"(p));
}
__device__ __forceinline__ void fma2(unsigned long long& d, unsigned long long a, unsigned long long b) {
    asm("fma.rn.f32x2 %0, %1, %2, %0;" : "+l"(d) : "l"(a), "l"(b));
}
__device__ __forceinline__ void cp_async16(void* smem_dst, const void* gmem_src) {
    unsigned sa = (unsigned)__cvta_generic_to_shared(smem_dst);
    asm volatile("cp.async.cg.shared.global [%0], [%1], 16;" :: "r"(sa), "l"(gmem_src));
}
__device__ __forceinline__ void cp_commit() { asm volatile("cp.async.commit_group;"); }
__device__ __forceinline__ void cp_wait0()  { asm volatile("cp.async.wait_group 0;" ::: "memory"); }

// ---------------------------------------------------------------------------
// Encoder: states0[b][t][:] = embed[sent[b][t]] @ W_enc + b_enc
// ---------------------------------------------------------------------------
__global__ void encode_kernel(const int* __restrict__ sent,
                              const float* __restrict__ emb,
                              const float* __restrict__ W,
                              const float* __restrict__ bias) {
    __shared__ float se[16][WD];
    const int tok0 = blockIdx.x * 16;
    const int tid = threadIdx.x;
    for (int i = tid; i < 16 * WD; i += 256) {
        int t = i / WD, k = i - t * WD;
        se[t][k] = emb[(size_t)sent[tok0 + t] * WD + k];
    }
    __syncthreads();
    const int n = tid;
    float acc[16];
    float bv = bias[n];
#pragma unroll
    for (int t = 0; t < 16; t++) acc[t] = bv;
    for (int k = 0; k < WD; k++) {
        float w = W[k * MD + n];
#pragma unroll
        for (int t = 0; t < 16; t++) acc[t] += se[t][k] * w;
    }
    float* out = g_states[0];
#pragma unroll
    for (int t = 0; t < 16; t++) out[(size_t)(tok0 + t) * MD + n] = acc[t];
}

// ---------------------------------------------------------------------------
// Fully fused layer kernel: (optional) previous-layer softmax+combine computed
// on the fly (prologue weights + fused X loader, materializing new states),
// then GEMM + TreeLSTM cell + logit partial.
// Grid: (ceil(P/BM), NB, 2). 128 threads (4 warps); warp ty owns TM rows,
// lane tx owns packed gate-col pair {j0+2tx, j0+2tx+1} across all 5 gates.
// Pp = P+1 for fused layers; Pp = 0 for the first layer (direct state reads).
// ---------------------------------------------------------------------------
template <int TM>
__global__ __launch_bounds__(128, 2)
void gates_gemm(const float* __restrict__ Wc, const float* __restrict__ bc,
                const float* __restrict__ Wsel, int P, int Pp, int sin, int cw) {
    constexpr int BM = TM * 4;
    __shared__ float Xs[2][BKT][XP];
    __shared__ float Ws[2][BKT * 320];     // [k][g*64 + j]
    __shared__ float wcl[64], wcr[64], wpr[64], sred[64];
    __shared__ float s_mx, s_tt;

    const float* __restrict__ Sin = g_states[sin];
    float* __restrict__ Sout = g_states[sin ^ 1];
    const float* __restrict__ Cin = g_comp[cw ^ 1];
    float* __restrict__ Cout = g_comp[cw];
    const float* __restrict__ Lin = g_lgpart[cw ^ 1];
    float* __restrict__ Lout = g_lgpart[cw];

    const int tid = threadIdx.x;
    const int tx = tid & 31, ty = tid >> 5;
    const int pt = blockIdx.x, b = blockIdx.y, jc = blockIdx.z;
    const int j0 = jc * 64;
    const int p0 = pt * BM;
    const int rows = min(BM, P - p0);

    // ---- Prologue: previous layer's softmax weights (per-batch, redundant) ----
    if (Pp > 0) {
        if (tid < 64) {
            float l = -3.0e38f;
            if (tid < Pp) {
                float2 v = *reinterpret_cast<const float2*>(Lin + ((size_t)b * Pp + tid) * 2);
                l = v.x + v.y;
            }
            wcl[tid] = l;
        }
        __syncthreads();
        if (tid < 32) {
            float v = fmaxf(wcl[tid], wcl[tid + 32]);
            for (int o = 16; o > 0; o >>= 1) v = fmaxf(v, __shfl_xor_sync(0xFFFFFFFFu, v, o));
            if (tid == 0) s_mx = v;
        }
        __syncthreads();
        if (tid < 64) {
            float e = (tid < Pp) ? __expf(wcl[tid] - s_mx) : 0.f;
            wcr[tid] = e; sred[tid] = e;
        }
        __syncthreads();
        for (int off = 1; off < 64; off <<= 1) {
            float v = 0.f;
            if (tid < 64) { v = sred[tid]; if (tid >= off) v += sred[tid - off]; }
            __syncthreads();
            if (tid < 64) sred[tid] = v;
            __syncthreads();
        }
        if (tid == 0) s_tt = sred[Pp - 1];
        __syncthreads();
        if (tid < 64) {
            float inv = 1.f / s_tt;
            float e = wcr[tid], cv = sred[tid];
            wpr[tid] = e * inv;                // probs
            wcr[tid] = (cv - e) * inv;         // copy_right
            wcl[tid] = (s_tt - cv) * inv;      // copy_left
        }
        __syncthreads();
    }

    // ---- X loader: row mA, quad kqA; on-the-fly combine + materialize ----
    const int mA = tid >> 1;
    const int kqA = tid & 1;
    const bool hasA = (mA < rows);
    const int pA = p0 + mA;

    unsigned long long acc[TM][5];
#pragma unroll
    for (int i = 0; i < TM; i++)
#pragma unroll
        for (int g = 0; g < 5; g++) acc[i][g] = 0ull;

    float4 xr;

    auto prefW = [&](int kt, int buf) {
        const float* base = Wc + (size_t)kt * 640 + j0;
#pragma unroll
        for (int it = 0; it < 5; it++) {
            int I = it * 128 + tid;
            int chunk = I >> 4;            // 0..39  (k*5+g)
            int j4 = I & 15;
            int k = chunk / 5;
            int g = chunk - k * 5;
            cp_async16(&Ws[buf][chunk * 64 + j4 * 4],
                       base + (size_t)k * 640 + g * 128 + j4 * 4);
        }
    };
    auto ldX = [&](int kt) {
        if (hasA) {
            int kg = kt + kqA * 4;
            int half = (kg >= HF) ? 1 : 0;
            int q = pA + half;
            int d = kg - (half ? HF : 0);
            const float* sp = Sin + ((size_t)b * SEQ + q) * MD + d;
            if (Pp == 0) {
                xr = *reinterpret_cast<const float4*>(sp);
            } else {
                float4 s0 = *reinterpret_cast<const float4*>(sp);
                float4 s1 = *reinterpret_cast<const float4*>(sp + MD);
                float4 c0 = *reinterpret_cast<const float4*>(Cin + ((size_t)b * Pp + q) * MD + d);
                float a = wcl[q], rr = wcr[q], pw = wpr[q];
                xr.x = a * s0.x + rr * s1.x + pw * c0.x;
                xr.y = a * s0.y + rr * s1.y + pw * c0.y;
                xr.z = a * s0.z + rr * s1.z + pw * c0.z;
                xr.w = a * s0.w + rr * s1.w + pw * c0.w;
                *reinterpret_cast<float4*>(Sout + ((size_t)b * SEQ + q) * MD + d) = xr;
            }
        }
    };
    auto stX = [&](int buf) {
        if (hasA) {
            float* xp = &Xs[buf][kqA * 4][mA];
            xp[0 * XP] = xr.x; xp[1 * XP] = xr.y;
            xp[2 * XP] = xr.z; xp[3 * XP] = xr.w;
        }
    };

    // Prologue: tile 0
    prefW(0, 0);
    cp_commit();
    ldX(0);
    stX(0);
    cp_wait0();
    __syncthreads();

    int buf = 0;
    for (int u = 0; u < NKT; u++, buf ^= 1) {
        if (u + 1 < NKT) {
            prefW((u + 1) * BKT, buf ^ 1);
            cp_commit();
            ldX((u + 1) * BKT);
        }
        // W-operand register double-buffer: break LDS->FFMA dependency
        unsigned long long w0, w1, w2, w3, w4, n0, n1, n2, n3, n4;
        {
            const float* wp = &Ws[buf][0] + 2 * tx;
            w0 = *reinterpret_cast<const unsigned long long*>(wp);
            w1 = *reinterpret_cast<const unsigned long long*>(wp + 64);
            w2 = *reinterpret_cast<const unsigned long long*>(wp + 128);
            w3 = *reinterpret_cast<const unsigned long long*>(wp + 192);
            w4 = *reinterpret_cast<const unsigned long long*>(wp + 256);
        }
#pragma unroll
        for (int k = 0; k < BKT; k++) {
            if (k + 1 < BKT) {
                const float* wp = &Ws[buf][(k + 1) * 320] + 2 * tx;
                n0 = *reinterpret_cast<const unsigned long long*>(wp);
                n1 = *reinterpret_cast<const unsigned long long*>(wp + 64);
                n2 = *reinterpret_cast<const unsigned long long*>(wp + 128);
                n3 = *reinterpret_cast<const unsigned long long*>(wp + 192);
                n4 = *reinterpret_cast<const unsigned long long*>(wp + 256);
            }
            const float* xp = &Xs[buf][k][ty * TM];
#pragma unroll
            for (int i = 0; i < TM; i += 2) {
                float2 v = *reinterpret_cast<const float2*>(xp + i);
                unsigned long long a0 = pack2(v.x, v.x);
                unsigned long long a1 = pack2(v.y, v.y);
                fma2(acc[i + 0][0], a0, w0); fma2(acc[i + 0][1], a0, w1);
                fma2(acc[i + 0][2], a0, w2); fma2(acc[i + 0][3], a0, w3);
                fma2(acc[i + 0][4], a0, w4);
                fma2(acc[i + 1][0], a1, w0); fma2(acc[i + 1][1], a1, w1);
                fma2(acc[i + 1][2], a1, w2); fma2(acc[i + 1][3], a1, w3);
                fma2(acc[i + 1][4], a1, w4);
            }
            if (k + 1 < BKT) { w0 = n0; w1 = n1; w2 = n2; w3 = n3; w4 = n4; }
        }
        if (u + 1 < NKT) stX(buf ^ 1);
        cp_wait0();
        __syncthreads();
    }

    // ---- Epilogue: on-the-fly c_l/c_r (+ materialize), cell, comp, logits ----
    const int j = j0 + 2 * tx;
    float2 wsh = *reinterpret_cast<const float2*>(Wsel + j);
    float2 wsc = *reinterpret_cast<const float2*>(Wsel + HF + j);
    float2 bb0 = *reinterpret_cast<const float2*>(bc + j);
    float2 bb1 = *reinterpret_cast<const float2*>(bc + 128 + j);
    float2 bb2 = *reinterpret_cast<const float2*>(bc + 256 + j);
    float2 bb3 = *reinterpret_cast<const float2*>(bc + 384 + j);
    float2 bb4 = *reinterpret_cast<const float2*>(bc + 512 + j);
#pragma unroll
    for (int i = 0; i < TM; i++) {
        int p = p0 + ty * TM + i;
        if (p >= P) continue;              // warp-uniform
        float2 cl2, cr2;
        const float* sp = Sin + ((size_t)b * SEQ + p) * MD + HF + j;
        if (Pp == 0) {
            cl2 = *reinterpret_cast<const float2*>(sp);
            cr2 = *reinterpret_cast<const float2*>(sp + MD);
        } else {
            float2 sA = *reinterpret_cast<const float2*>(sp);
            float2 sB = *reinterpret_cast<const float2*>(sp + MD);
            float2 sC = *reinterpret_cast<const float2*>(sp + 2 * MD);
            float2 cA = *reinterpret_cast<const float2*>(Cin + ((size_t)b * Pp + p) * MD + HF + j);
            float2 cB = *reinterpret_cast<const float2*>(Cin + ((size_t)b * Pp + p + 1) * MD + HF + j);
            cl2.x = wcl[p] * sA.x + wcr[p] * sB.x + wpr[p] * cA.x;
            cl2.y = wcl[p] * sA.y + wcr[p] * sB.y + wpr[p] * cA.y;
            cr2.x = wcl[p + 1] * sB.x + wcr[p + 1] * sC.x + wpr[p + 1] * cB.x;
            cr2.y = wcl[p + 1] * sB.y + wcr[p + 1] * sC.y + wpr[p + 1] * cB.y;
            *reinterpret_cast<float2*>(Sout + ((size_t)b * SEQ + p) * MD + HF + j) = cl2;
            *reinterpret_cast<float2*>(Sout + ((size_t)b * SEQ + p + 1) * MD + HF + j) = cr2;
        }
        float a0, a1, i0, i1, f10, f11, f20, f21, o0, o1;
        unpack2(acc[i][0], a0, a1);
        unpack2(acc[i][1], i0, i1);
        unpack2(acc[i][2], f10, f11);
        unpack2(acc[i][3], f20, f21);
        unpack2(acc[i][4], o0, o1);
        float c0 = tanh_f(a0 + bb0.x) * sig_f(i0 + bb1.x)
                 + sig_f(f10 + bb2.x) * cl2.x + sig_f(f20 + bb3.x) * cr2.x;
        float c1 = tanh_f(a1 + bb0.y) * sig_f(i1 + bb1.y)
                 + sig_f(f11 + bb2.y) * cl2.y + sig_f(f21 + bb3.y) * cr2.y;
        float h0 = sig_f(o0 + bb4.x) * tanh_f(c0);
        float h1 = sig_f(o1 + bb4.y) * tanh_f(c1);
        float* cp = Cout + ((size_t)b * P + p) * MD;
        *reinterpret_cast<float2*>(cp + j) = make_float2(h0, h1);
        *reinterpret_cast<float2*>(cp + HF + j) = make_float2(c0, c1);
        float part = h0 * wsh.x + h1 * wsh.y + c0 * wsc.x + c1 * wsc.y;
#pragma unroll
        for (int o = 16; o > 0; o >>= 1) part += __shfl_xor_sync(0xFFFFFFFFu, part, o);
        if (tx == 0) Lout[((size_t)b * P + p) * 2 + jc] = part;
    }
}

// ---------------------------------------------------------------------------
// Final MLP. Layer P=1 output state == its comp row (softmax over 1 logit).
// ---------------------------------------------------------------------------
__global__ void mlp_kernel(const float* __restrict__ W1, const float* __restrict__ b1,
                           const float* __restrict__ W2, const float* __restrict__ b2,
                           const float* __restrict__ Wo, const float* __restrict__ bo,
                           float* __restrict__ out, int cpar) {
    const int b = blockIdx.x, tid = threadIdx.x;
    __shared__ float h0[MD];
    __shared__ float h1[MLPD];
    __shared__ float h2[MLPD];
    __shared__ float red[256];
    const float* S = g_comp[cpar] + (size_t)b * MD;   // layer P=1: row b*1+0
    for (int i = tid; i < MD; i += 256) h0[i] = S[i];
    __syncthreads();
#pragma unroll
    for (int ni = 0; ni < MLPD / 256; ni++) {
        int n = tid + ni * 256;
        float acc = b1[n];
        for (int k = 0; k < MD; k++) acc += h0[k] * W1[(size_t)k * MLPD + n];
        h1[n] = fmaxf(acc, 0.f);
    }
    __syncthreads();
#pragma unroll
    for (int ni = 0; ni < MLPD / 256; ni++) {
        int n = tid + ni * 256;
        float acc = b2[n];
        for (int k = 0; k < MLPD; k++) acc += h1[k] * W2[(size_t)k * MLPD + n];
        h2[n] = fmaxf(acc, 0.f);
    }
    __syncthreads();
    for (int c = 0; c < NC; c++) {
        float part = 0.f;
        for (int k = tid; k < MLPD; k += 256) part += h2[k] * Wo[(size_t)k * NC + c];
        red[tid] = part;
        __syncthreads();
        for (int s = 128; s > 0; s >>= 1) {
            if (tid < s) red[tid] += red[tid + s];
            __syncthreads();
        }
        if (tid == 0) out[b * NC + c] = red[0] + bo[c];
        __syncthreads();
    }
}

// ---------------------------------------------------------------------------
extern "C" void kernel_launch(void* const* d_in, const int* in_sizes, int n_in,
                              void* d_out, int out_size) {
    const int*   sent   = (const int*)  d_in[0];
    const float* emb    = (const float*)d_in[1];
    const float* W_enc  = (const float*)d_in[2];
    const float* b_enc  = (const float*)d_in[3];
    const float* W_comp = (const float*)d_in[4];
    const float* b_comp = (const float*)d_in[5];
    const float* W_sel  = (const float*)d_in[6];
    // d_in[7] = b_sel (constant shift, softmax-invariant — not needed)
    const float* W1     = (const float*)d_in[8];
    const float* b1     = (const float*)d_in[9];
    const float* W2     = (const float*)d_in[10];
    const float* b2     = (const float*)d_in[11];
    const float* Wo     = (const float*)d_in[12];
    const float* bo     = (const float*)d_in[13];
    float* out = (float*)d_out;

    encode_kernel<<<NB * SEQ / 16, 256>>>(sent, emb, W_enc, b_enc);

    // Layer P=63: direct state reads (Pp=0), writes comp parity 1.
    {
        dim3 g((63 + 31) / 32, NB, 2);
        gates_gemm<8><<<g, 128>>>(W_comp, b_comp, W_sel, 63, 0, 0, 1);
    }
    // Layers P=62..1: fused combine-on-the-fly. comp parity = P&1.
    int sin = 0;
    for (int P = 62; P >= 1; --P) {
        int cw = P & 1;
        int Pp = P + 1;
        if (P >= 30) {
            dim3 g((P + 31) / 32, NB, 2);
            gates_gemm<8><<<g, 128>>>(W_comp, b_comp, W_sel, P, Pp, sin, cw);
        } else if (P >= 8) {
            dim3 g((P + 15) / 16, NB, 2);
            gates_gemm<4><<<g, 128>>>(W_comp, b_comp, W_sel, P, Pp, sin, cw);
        } else {
            dim3 g(1, NB, 2);
            gates_gemm<2><<<g, 128>>>(W_comp, b_comp, W_sel, P, Pp, sin, cw);
        }
        sin ^= 1;
    }

    mlp_kernel<<<NB, 256>>>(W1, b1, W2, b2, Wo, bo, out, 1);  // P=1 parity = 1
}

// round 11
// speedup vs baseline: 1.2693x; 1.2693x over previous
#include <cuda_runtime.h>
#include <math.h>

#define NB 64          // batch
#define SEQ 64         // seq len
#define MD 256         // model dim
#define HF 128         // half
#define WD 300         // word dim
#define MLPD 1024
#define NC 3
#define BKT 16         // K tile
#define NKT (MD / BKT) // 16 k-tiles
#define XP 20          // Xs row stride in floats (BM=16 + pad; 16B-aligned rows)

// Scratch (device globals — no runtime allocation allowed)
__device__ float g_states[2][NB * SEQ * MD];     // ping-pong state buffers
__device__ float g_comp[NB * (SEQ - 1) * MD];    // TreeLSTM [h,c] outputs
__device__ float g_lgpart[NB * (SEQ - 1) * 2];   // selection-logit partials (2 j-chunks)

__device__ __forceinline__ float sig_f(float x) { return 1.0f / (1.0f + __expf(-x)); }
__device__ __forceinline__ float tanh_f(float x) { return 1.0f - 2.0f / (__expf(2.0f * x) + 1.0f); }

// Packed f32x2 helpers (sm_100a; ptxas never auto-fuses these)
__device__ __forceinline__ unsigned long long pack2(float lo, float hi) {
    unsigned long long p;
    asm("mov.b64 %0, {%1, %2};" : "=l"(p) : "f"(lo), "f"(hi));
    return p;
}
__device__ __forceinline__ void unpack2(unsigned long long p, float& lo, float& hi) {
    asm("mov.b64 {%0, %1}, %2;" : "=f"(lo), "=f"(hi) : "l"(p));
}
__device__ __forceinline__ void fma2(unsigned long long& d, unsigned long long a, unsigned long long b) {
    asm("fma.rn.f32x2 %0, %1, %2, %0;" : "+l"(d) : "l"(a), "l"(b));
}
__device__ __forceinline__ void cp_async16(void* smem_dst, const void* gmem_src) {
    unsigned sa = (unsigned)__cvta_generic_to_shared(smem_dst);
    asm volatile("cp.async.cg.shared.global [%0], [%1], 16;" :: "r"(sa), "l"(gmem_src));
}
__device__ __forceinline__ void cp_commit() { asm volatile("cp.async.commit_group;"); }
__device__ __forceinline__ void cp_wait0()  { asm volatile("cp.async.wait_group 0;" ::: "memory"); }

// ---------------------------------------------------------------------------
// Encoder: states0[b][t][:] = embed[sent[b][t]] @ W_enc + b_enc
// ---------------------------------------------------------------------------
__global__ void encode_kernel(const int* __restrict__ sent,
                              const float* __restrict__ emb,
                              const float* __restrict__ W,
                              const float* __restrict__ bias) {
    __shared__ float se[16][WD];
    const int tok0 = blockIdx.x * 16;
    const int tid = threadIdx.x;
    for (int i = tid; i < 16 * WD; i += 256) {
        int t = i / WD, k = i - t * WD;
        se[t][k] = emb[(size_t)sent[tok0 + t] * WD + k];
    }
    __syncthreads();
    const int n = tid;
    float acc[16];
    float bv = bias[n];
#pragma unroll
    for (int t = 0; t < 16; t++) acc[t] = bv;
    for (int k = 0; k < WD; k++) {
        float w = W[k * MD + n];
#pragma unroll
        for (int t = 0; t < 16; t++) acc[t] += se[t][k] * w;
    }
    float* out = g_states[0];
#pragma unroll
    for (int t = 0; t < 16; t++) out[(size_t)(tok0 + t) * MD + n] = acc[t];
}

// ---------------------------------------------------------------------------
// Fused GEMM + TreeLSTM cell + logit partial.
// 128 threads (4 warps), BM = TM*4 rows x 64 gate-cols (jc) x 5 gates.
// TM=4 -> grid 2x larger than R8 (496 blocks @P=62): 13.4 warps/SM for
// latency hiding. Lane tx owns packed col pair {j0+2tx, j0+2tx+1}; warp ty
// owns TM rows. W tile double-buffered via cp.async AND register-staged.
// ---------------------------------------------------------------------------
template <int TM>
__global__ __launch_bounds__(128, 4)
void gates_gemm(const float* __restrict__ Wc, const float* __restrict__ bc,
                const float* __restrict__ Wsel, int P, int in) {
    constexpr int BM = TM * 4;
    __shared__ float Xs[2][BKT][XP];
    __shared__ float Ws[2][BKT * 320];     // [k][g*64 + j]

    const float* __restrict__ S = g_states[in];
    const int tid = threadIdx.x;
    const int tx = tid & 31, ty = tid >> 5;
    const int jc = blockIdx.y;             // 0 or 1
    const int j0 = jc * 64;
    const int m0 = blockIdx.x * BM;

    // X loader: row mA, quad kqA (BM rows x BKT/4 quads); BM=16 -> 64 loaders
    const int mA = tid >> 2;
    const int kqA = tid & 3;
    const bool hasA = (mA < BM);
    int roffA = 0;
    if (hasA) {
        int r = m0 + mA;
        int b = r / P;
        roffA = b * (SEQ * MD) + (r - b * P) * MD;
    }

    unsigned long long acc[TM][5];
#pragma unroll
    for (int i = 0; i < TM; i++)
#pragma unroll
        for (int g = 0; g < 5; g++) acc[i][g] = 0ull;

    float4 xr;

    // W prefetch: BKT*80 = 1280 float4, 10 per thread. chunk=(k*5+g).
    auto prefW = [&](int kt, int buf) {
        const float* base = Wc + (size_t)kt * 640 + j0;
#pragma unroll
        for (int it = 0; it < 10; it++) {
            int I = it * 128 + tid;
            int chunk = I >> 4;            // 0..79
            int j4 = I & 15;
            int k = chunk / 5;
            int g = chunk - k * 5;
            cp_async16(&Ws[buf][chunk * 64 + j4 * 4],
                       base + (size_t)k * 640 + g * 128 + j4 * 4);
        }
    };
    auto ldX = [&](int kt) {
        if (hasA) {
            int kg = kt + kqA * 4;
            int xoff = kg + ((kg >= HF) ? HF : 0);
            xr = *reinterpret_cast<const float4*>(S + roffA + xoff);
        }
    };
    auto stX = [&](int buf) {
        if (hasA) {
            float* xp = &Xs[buf][kqA * 4][mA];
            xp[0 * XP] = xr.x; xp[1 * XP] = xr.y;
            xp[2 * XP] = xr.z; xp[3 * XP] = xr.w;
        }
    };

    // Prologue: tile 0
    prefW(0, 0);
    cp_commit();
    ldX(0);
    stX(0);
    cp_wait0();
    __syncthreads();

    int buf = 0;
    for (int u = 0; u < NKT; u++, buf ^= 1) {
        if (u + 1 < NKT) {
            prefW((u + 1) * BKT, buf ^ 1);
            cp_commit();
            ldX((u + 1) * BKT);
        }
        // W-operand register double-buffer: break LDS->FFMA dependency
        unsigned long long w0, w1, w2, w3, w4, n0, n1, n2, n3, n4;
        {
            const float* wp = &Ws[buf][0] + 2 * tx;
            w0 = *reinterpret_cast<const unsigned long long*>(wp);
            w1 = *reinterpret_cast<const unsigned long long*>(wp + 64);
            w2 = *reinterpret_cast<const unsigned long long*>(wp + 128);
            w3 = *reinterpret_cast<const unsigned long long*>(wp + 192);
            w4 = *reinterpret_cast<const unsigned long long*>(wp + 256);
        }
#pragma unroll
        for (int k = 0; k < BKT; k++) {
            if (k + 1 < BKT) {
                const float* wp = &Ws[buf][(k + 1) * 320] + 2 * tx;
                n0 = *reinterpret_cast<const unsigned long long*>(wp);
                n1 = *reinterpret_cast<const unsigned long long*>(wp + 64);
                n2 = *reinterpret_cast<const unsigned long long*>(wp + 128);
                n3 = *reinterpret_cast<const unsigned long long*>(wp + 192);
                n4 = *reinterpret_cast<const unsigned long long*>(wp + 256);
            }
            const float* xp = &Xs[buf][k][ty * TM];
#pragma unroll
            for (int i = 0; i < TM; i += 2) {
                float2 v = *reinterpret_cast<const float2*>(xp + i);
                unsigned long long a0 = pack2(v.x, v.x);
                unsigned long long a1 = pack2(v.y, v.y);
                fma2(acc[i + 0][0], a0, w0); fma2(acc[i + 0][1], a0, w1);
                fma2(acc[i + 0][2], a0, w2); fma2(acc[i + 0][3], a0, w3);
                fma2(acc[i + 0][4], a0, w4);
                fma2(acc[i + 1][0], a1, w0); fma2(acc[i + 1][1], a1, w1);
                fma2(acc[i + 1][2], a1, w2); fma2(acc[i + 1][3], a1, w3);
                fma2(acc[i + 1][4], a1, w4);
            }
            if (k + 1 < BKT) { w0 = n0; w1 = n1; w2 = n2; w3 = n3; w4 = n4; }
        }
        if (u + 1 < NKT) stX(buf ^ 1);
        cp_wait0();
        __syncthreads();
    }

    // Epilogue: bias + TreeLSTM cell + comp write + logit partial (2 cols/lane)
    const int j = j0 + 2 * tx;
    float2 wsh = *reinterpret_cast<const float2*>(Wsel + j);
    float2 wsc = *reinterpret_cast<const float2*>(Wsel + HF + j);
    float2 bb0 = *reinterpret_cast<const float2*>(bc + j);
    float2 bb1 = *reinterpret_cast<const float2*>(bc + 128 + j);
    float2 bb2 = *reinterpret_cast<const float2*>(bc + 256 + j);
    float2 bb3 = *reinterpret_cast<const float2*>(bc + 384 + j);
    float2 bb4 = *reinterpret_cast<const float2*>(bc + 512 + j);
#pragma unroll
    for (int i = 0; i < TM; i++) {
        int r = m0 + ty * TM + i;
        int b = r / P;
        int roff = b * (SEQ * MD) + (r - b * P) * MD;
        float2 cl = *reinterpret_cast<const float2*>(S + roff + HF + j);
        float2 cr = *reinterpret_cast<const float2*>(S + roff + MD + HF + j);
        float a0, a1, i0, i1, f10, f11, f20, f21, o0, o1;
        unpack2(acc[i][0], a0, a1);
        unpack2(acc[i][1], i0, i1);
        unpack2(acc[i][2], f10, f11);
        unpack2(acc[i][3], f20, f21);
        unpack2(acc[i][4], o0, o1);
        float c0 = tanh_f(a0 + bb0.x) * sig_f(i0 + bb1.x)
                 + sig_f(f10 + bb2.x) * cl.x + sig_f(f20 + bb3.x) * cr.x;
        float c1 = tanh_f(a1 + bb0.y) * sig_f(i1 + bb1.y)
                 + sig_f(f11 + bb2.y) * cl.y + sig_f(f21 + bb3.y) * cr.y;
        float h0 = sig_f(o0 + bb4.x) * tanh_f(c0);
        float h1 = sig_f(o1 + bb4.y) * tanh_f(c1);
        float* cp = g_comp + (size_t)r * MD;
        *reinterpret_cast<float2*>(cp + j) = make_float2(h0, h1);
        *reinterpret_cast<float2*>(cp + HF + j) = make_float2(c0, c1);
        float part = h0 * wsh.x + h1 * wsh.y + c0 * wsc.x + c1 * wsc.y;
#pragma unroll
        for (int o = 16; o > 0; o >>= 1) part += __shfl_xor_sync(0xFFFFFFFFu, part, o);
        if (tx == 0) g_lgpart[r * 2 + jc] = part;
    }
}

// ---------------------------------------------------------------------------
// Per-layer softmax + soft state update. 4 blocks per batch row.
// ---------------------------------------------------------------------------
__global__ __launch_bounds__(256)
void update_kernel(int P, int in) {
    __shared__ float lg[64], es[64], csn[64];
    __shared__ float prw[64], clw[64], crw[64];
    __shared__ float s_max, s_inv, s_tot;
    const int b = blockIdx.x >> 2, q = blockIdx.x & 3;
    const int tid = threadIdx.x;

    if (tid < 64) {
        float l = -3.0e38f;
        if (tid < P) {
            float2 v = *reinterpret_cast<const float2*>(g_lgpart + (((size_t)b * P + tid) << 1));
            l = v.x + v.y;
        }
        lg[tid] = l;
    }
    __syncthreads();
    if (tid < 32) {
        float v = fmaxf(lg[tid], lg[tid + 32]);
        for (int o = 16; o > 0; o >>= 1) v = fmaxf(v, __shfl_xor_sync(0xFFFFFFFFu, v, o));
        if (tid == 0) s_max = v;
    }
    __syncthreads();
    if (tid < 64) {
        float e = (tid < P) ? __expf(lg[tid] - s_max) : 0.f;
        es[tid] = e; csn[tid] = e;
    }
    __syncthreads();
    for (int off = 1; off < 64; off <<= 1) {
        float v = 0.f;
        if (tid < 64) { v = csn[tid]; if (tid >= off) v += csn[tid - off]; }
        __syncthreads();
        if (tid < 64) csn[tid] = v;
        __syncthreads();
    }
    if (tid == 0) { s_tot = csn[P - 1]; s_inv = 1.f / csn[P - 1]; }
    __syncthreads();
    if (tid < 64) {
        float inv = s_inv, e = es[tid], cv = csn[tid];
        prw[tid] = e * inv;
        crw[tid] = (cv - e) * inv;
        clw[tid] = (s_tot - cv) * inv;
    }
    __syncthreads();
    const float* Sb = g_states[in] + b * SEQ * MD;
    float* Ob = g_states[in ^ 1] + b * SEQ * MD;
    const float* Cb = g_comp + (size_t)b * P * MD;
    for (int p = q; p < P; p += 4) {
        Ob[p * MD + tid] = clw[p] * Sb[p * MD + tid]
                         + crw[p] * Sb[(p + 1) * MD + tid]
                         + prw[p] * Cb[p * MD + tid];
    }
}

// ---------------------------------------------------------------------------
// Final MLP: relu(relu(h@W1+b1)@W2+b2)@W_out + b_out. One block per row.
// ---------------------------------------------------------------------------
__global__ void mlp_kernel(const float* __restrict__ W1, const float* __restrict__ b1,
                           const float* __restrict__ W2, const float* __restrict__ b2,
                           const float* __restrict__ Wo, const float* __restrict__ bo,
                           float* __restrict__ out, int in) {
    const int b = blockIdx.x, tid = threadIdx.x;
    __shared__ float h0[MD];
    __shared__ float h1[MLPD];
    __shared__ float h2[MLPD];
    __shared__ float red[256];
    const float* S = g_states[in] + (size_t)b * SEQ * MD;
    for (int i = tid; i < MD; i += 256) h0[i] = S[i];
    __syncthreads();
#pragma unroll
    for (int ni = 0; ni < MLPD / 256; ni++) {
        int n = tid + ni * 256;
        float acc = b1[n];
        for (int k = 0; k < MD; k++) acc += h0[k] * W1[(size_t)k * MLPD + n];
        h1[n] = fmaxf(acc, 0.f);
    }
    __syncthreads();
#pragma unroll
    for (int ni = 0; ni < MLPD / 256; ni++) {
        int n = tid + ni * 256;
        float acc = b2[n];
        for (int k = 0; k < MLPD; k++) acc += h1[k] * W2[(size_t)k * MLPD + n];
        h2[n] = fmaxf(acc, 0.f);
    }
    __syncthreads();
    for (int c = 0; c < NC; c++) {
        float part = 0.f;
        for (int k = tid; k < MLPD; k += 256) part += h2[k] * Wo[(size_t)k * NC + c];
        red[tid] = part;
        __syncthreads();
        for (int s = 128; s > 0; s >>= 1) {
            if (tid < s) red[tid] += red[tid + s];
            __syncthreads();
        }
        if (tid == 0) out[b * NC + c] = red[0] + bo[c];
        __syncthreads();
    }
}

// ---------------------------------------------------------------------------
extern "C" void kernel_launch(void* const* d_in, const int* in_sizes, int n_in,
                              void* d_out, int out_size) {
    const int*   sent   = (const int*)  d_in[0];
    const float* emb    = (const float*)d_in[1];
    const float* W_enc  = (const float*)d_in[2];
    const float* b_enc  = (const float*)d_in[3];
    const float* W_comp = (const float*)d_in[4];
    const float* b_comp = (const float*)d_in[5];
    const float* W_sel  = (const float*)d_in[6];
    // d_in[7] = b_sel (constant shift, softmax-invariant — not needed)
    const float* W1     = (const float*)d_in[8];
    const float* b1     = (const float*)d_in[9];
    const float* W2     = (const float*)d_in[10];
    const float* b2     = (const float*)d_in[11];
    const float* Wo     = (const float*)d_in[12];
    const float* bo     = (const float*)d_in[13];
    float* out = (float*)d_out;

    encode_kernel<<<NB * SEQ / 16, 256>>>(sent, emb, W_enc, b_enc);

    int cur = 0;
    for (int P = SEQ - 1; P >= 1; --P) {
        if (P >= 8) {
            dim3 grid(NB * P / 16, 2);   // BM=16 (TM=4) -> 2x warp pool vs R8
            gates_gemm<4><<<grid, 128>>>(W_comp, b_comp, W_sel, P, cur);
        } else {
            dim3 grid(NB * P / 8, 2);    // BM=8 (TM=2)
            gates_gemm<2><<<grid, 128>>>(W_comp, b_comp, W_sel, P, cur);
        }
        update_kernel<<<NB * 4, 256>>>(P, cur);
        cur ^= 1;
    }

    mlp_kernel<<<NB, 256>>>(W1, b1, W2, b2, Wo, bo, out, 1);  // 63 layers -> parity 1
}